// round 14
// baseline (speedup 1.0000x reference)
#include <cuda_runtime.h>
#include <cuda_bf16.h>
#include <cuda_fp16.h>
#include <math.h>
#include <stdint.h>

// Problem constants
#define SB   2048
#define BB   2
#define DD   1024
#define NH   16
#define HDIM 64
#define MR   (BB*SB)       // 4096

// Scratch (device globals)
__device__ __align__(256) __half g_xh[(size_t)MR*DD];
__device__ __align__(256) __half g_wh[4][(size_t)DD*DD];
__device__ __align__(256) __half g_wl[4][(size_t)DD*DD];
__device__ __align__(256) __half g_ch[(size_t)MR*DD];          // ctx fp16
__device__ __align__(256) __nv_bfloat16 g_qhi[(size_t)MR*DD];  // [b,h,s,hd]
__device__ __align__(256) __nv_bfloat16 g_qlo[(size_t)MR*DD];
__device__ __align__(256) __nv_bfloat16 g_khi[(size_t)MR*DD];
__device__ __align__(256) __nv_bfloat16 g_klo[(size_t)MR*DD];
__device__ __align__(256) __half        g_vh [(size_t)MR*DD];

// ===========================================================================
// Helpers
// ===========================================================================
__device__ __forceinline__ uint32_t smem_u32(const void* p) {
    uint32_t a;
    asm("{ .reg .u64 t; cvta.to.shared.u64 t, %1; cvt.u32.u64 %0, t; }"
        : "=r"(a) : "l"(p));
    return a;
}

__device__ __forceinline__ void ldsm4(uint32_t* r, uint32_t a) {
    asm volatile("ldmatrix.sync.aligned.m8n8.x4.shared.b16 {%0,%1,%2,%3}, [%4];"
                 : "=r"(r[0]), "=r"(r[1]), "=r"(r[2]), "=r"(r[3]) : "r"(a));
}

__device__ __forceinline__ void ldsm4t(uint32_t* r, uint32_t a) {
    asm volatile("ldmatrix.sync.aligned.m8n8.x4.trans.shared.b16 {%0,%1,%2,%3}, [%4];"
                 : "=r"(r[0]), "=r"(r[1]), "=r"(r[2]), "=r"(r[3]) : "r"(a));
}

__device__ __forceinline__ void mma16816(float* c, const uint32_t* a, const uint32_t* b) {
    asm volatile(
        "mma.sync.aligned.m16n8k16.row.col.f32.bf16.bf16.f32 "
        "{%0,%1,%2,%3}, {%4,%5,%6,%7}, {%8,%9}, {%0,%1,%2,%3};"
        : "+f"(c[0]), "+f"(c[1]), "+f"(c[2]), "+f"(c[3])
        : "r"(a[0]), "r"(a[1]), "r"(a[2]), "r"(a[3]), "r"(b[0]), "r"(b[1]));
}

__device__ __forceinline__ void mma16816h(float* c, const uint32_t* a, const uint32_t* b) {
    asm volatile(
        "mma.sync.aligned.m16n8k16.row.col.f32.f16.f16.f32 "
        "{%0,%1,%2,%3}, {%4,%5,%6,%7}, {%8,%9}, {%0,%1,%2,%3};"
        : "+f"(c[0]), "+f"(c[1]), "+f"(c[2]), "+f"(c[3])
        : "r"(a[0]), "r"(a[1]), "r"(a[2]), "r"(a[3]), "r"(b[0]), "r"(b[1]));
}

__device__ __forceinline__ void cp16(uint32_t dst, const void* src) {
    asm volatile("cp.async.cg.shared.global [%0], [%1], 16;"
                 :: "r"(dst), "l"(src) : "memory");
}
#define CP_COMMIT asm volatile("cp.async.commit_group;" ::: "memory")
#define CP_WAIT1  asm volatile("cp.async.wait_group 1;"  ::: "memory")

__device__ __forceinline__ uint32_t pack2(__nv_bfloat16 a, __nv_bfloat16 b) {
    __nv_bfloat162 t = __halves2bfloat162(a, b);
    return *(uint32_t*)&t;
}

__device__ __forceinline__ uint32_t packsplit(float a, float b, uint32_t& lo) {
    __nv_bfloat16 ha = __float2bfloat16(a), hb = __float2bfloat16(b);
    lo = pack2(__float2bfloat16(a - __bfloat162float(ha)),
               __float2bfloat16(b - __bfloat162float(hb)));
    return pack2(ha, hb);
}

__device__ __forceinline__ uint32_t packsplit_h(float a, float b, uint32_t& lo) {
    __half ha = __float2half_rn(a), hb = __float2half_rn(b);
    __half2 l = __halves2half2(__float2half_rn(a - __half2float(ha)),
                               __float2half_rn(b - __half2float(hb)));
    lo = *(uint32_t*)&l;
    __half2 h = __halves2half2(ha, hb);
    return *(uint32_t*)&h;
}

__device__ __forceinline__ uint32_t packh2(float a, float b) {
    __half2 h = __floats2half2_rn(a, b);
    return *(uint32_t*)&h;
}

// ===========================================================================
// Convert: x -> fp16 single; W -> fp16 hi+lo. One launch, 5 segments.
// ===========================================================================
__global__ void convert_all(const float* __restrict__ x,
                            const float* __restrict__ Wq,
                            const float* __restrict__ Wk,
                            const float* __restrict__ Wv,
                            const float* __restrict__ Wo)
{
    const int seg = blockIdx.y;
    if (seg == 0) {
        int n4 = MR*DD/4;
        for (int i = blockIdx.x * blockDim.x + threadIdx.x; i < n4;
             i += gridDim.x * blockDim.x) {
            float4 v = ((const float4*)x)[i];
            ((uint2*)g_xh)[i] = make_uint2(packh2(v.x, v.y), packh2(v.z, v.w));
        }
        return;
    }
    const float* src = (seg == 1) ? Wq : (seg == 2) ? Wk : (seg == 3) ? Wv : Wo;
    __half* hi = g_wh[seg-1];
    __half* lo = g_wl[seg-1];
    int n4 = DD*DD/4;
    for (int i = blockIdx.x * blockDim.x + threadIdx.x; i < n4;
         i += gridDim.x * blockDim.x) {
        float4 v = ((const float4*)src)[i];
        uint32_t l01, l23;
        uint32_t h01 = packsplit_h(v.x, v.y, l01);
        uint32_t h23 = packsplit_h(v.z, v.w, l23);
        ((uint2*)hi)[i] = make_uint2(h01, h23);
        ((uint2*)lo)[i] = make_uint2(l01, l23);
    }
}

// ===========================================================================
// fp16 2-term GEMM mainloop (round-9/10 proven): K-step 32, 3 stages, wait1,
// XOR-swizzled 64B-pitch tiles. Stage = 3 tiles (A, Bh, Bl).
// ===========================================================================
#define GP_B        64
#define TILE_B      (128*GP_B)          // 8192
#define STAGE_B     (3*TILE_B)          // 24576
#define GSMEM       (3*STAGE_B)         // 73728

__device__ __forceinline__ uint32_t gsw(int row, int chunk) {
    return (uint32_t)(row * GP_B + ((chunk ^ ((row >> 1) & 3)) << 4));
}

__device__ __forceinline__ void gemm_mainloop(
    const __half* __restrict__ A,
    const __half* __restrict__ Bh, const __half* __restrict__ Bl,
    int m0, int n0, char* sm, float acc[4][4][4])
{
    const int tid = threadIdx.x;
    const uint32_t smb = smem_u32(sm);

    #pragma unroll
    for (int t = 0; t < 4; t++)
        #pragma unroll
        for (int n = 0; n < 4; n++)
            #pragma unroll
            for (int e = 0; e < 4; e++) acc[t][n][e] = 0.0f;

    auto load_stage = [&](int st, int k0) {
        uint32_t base = smb + st * STAGE_B;
        #pragma unroll
        for (int j = 0; j < 2; j++) {
            int idx = tid + j * 256;
            int r = idx >> 2, c = idx & 3;
            uint32_t doff = gsw(r, c);
            size_t sa = (size_t)(m0 + r) * DD + k0 + c * 8;
            size_t sb = (size_t)(n0 + r) * DD + k0 + c * 8;
            cp16(base + doff,            A  + sa);
            cp16(base + TILE_B + doff,   Bh + sb);
            cp16(base + 2*TILE_B + doff, Bl + sb);
        }
    };

    load_stage(0, 0);  CP_COMMIT;
    load_stage(1, 32); CP_COMMIT;

    const int wid = tid >> 5, lane = tid & 31;
    const int wm = (wid >> 2) * 64;
    const int wn = (wid & 3) * 32;
    const int arow = lane & 15;
    const int ack  = lane >> 4;
    const int brow = (lane & 7) + ((lane >> 4) << 3);
    const int bck  = (lane >> 3) & 1;

    int stage = 0;
    for (int kt = 0; kt < 32; kt++) {
        CP_WAIT1;
        __syncthreads();
        if (kt + 2 < 32) {
            int st2 = stage + 2; if (st2 >= 3) st2 -= 3;
            load_stage(st2, (kt + 2) * 32);
            CP_COMMIT;
        }

        uint32_t base = smb + stage * STAGE_B;
        uint32_t sA = base, sBh = base + TILE_B, sBl = base + 2*TILE_B;

        #pragma unroll
        for (int k16 = 0; k16 < 2; k16++) {
            uint32_t ah[4][4], bh[4][2], bl[4][2];
            #pragma unroll
            for (int t = 0; t < 4; t++)
                ldsm4(ah[t], sA + gsw(wm + t*16 + arow, k16*2 + ack));
            #pragma unroll
            for (int p = 0; p < 2; p++) {
                uint32_t bo = gsw(wn + p*16 + brow, k16*2 + bck);
                uint32_t r4[4];
                ldsm4(r4, sBh + bo);
                bh[2*p][0] = r4[0]; bh[2*p][1] = r4[1];
                bh[2*p+1][0] = r4[2]; bh[2*p+1][1] = r4[3];
                ldsm4(r4, sBl + bo);
                bl[2*p][0] = r4[0]; bl[2*p][1] = r4[1];
                bl[2*p+1][0] = r4[2]; bl[2*p+1][1] = r4[3];
            }
            #pragma unroll
            for (int t = 0; t < 4; t++)
                #pragma unroll
                for (int n = 0; n < 4; n++)
                    mma16816h(acc[t][n], ah[t], bh[n]);
            #pragma unroll
            for (int t = 0; t < 4; t++)
                #pragma unroll
                for (int n = 0; n < 4; n++)
                    mma16816h(acc[t][n], ah[t], bl[n]);
        }

        if (++stage == 3) stage = 0;
    }
}

// ---------------------------------------------------------------------------
// Q/K projection: uniform bf16 hi/lo epilogue. grid.x=16 (q:0-7, k:8-15)
// ---------------------------------------------------------------------------
__global__ __launch_bounds__(256, 2) void qk_gemm_mma()
{
    extern __shared__ char sm[];
    const int n0g = blockIdx.x * 128;
    const int m0  = blockIdx.y * 128;
    const int which = n0g >> 10;          // 0=q, 1=k
    const int nb    = n0g & 1023;

    __nv_bfloat16* OH = (which == 0) ? g_qhi : g_khi;
    __nv_bfloat16* OL = (which == 0) ? g_qlo : g_klo;

    float acc[4][4][4];
    gemm_mainloop(g_xh, g_wh[which], g_wl[which], m0, nb, sm, acc);

    const int tid = threadIdx.x, wid = tid >> 5, lane = tid & 31;
    const int wm = (wid >> 2) * 64, wn = (wid & 3) * 32;
    const int gid = lane >> 2, qid = lane & 3;

    #pragma unroll
    for (int t = 0; t < 4; t++) {
        #pragma unroll
        for (int n = 0; n < 4; n++) {
            int cc = nb + wn + n*8 + qid*2;
            int h = cc >> 6, hd = cc & 63;
            #pragma unroll
            for (int half = 0; half < 2; half++) {
                int row = m0 + wm + t*16 + gid + 8*half;
                int b = row >> 11, s = row & 2047;
                uint32_t lo;
                uint32_t hi = packsplit(acc[t][n][2*half], acc[t][n][2*half+1], lo);
                size_t off = (((size_t)(b*NH + h))*SB + s)*HDIM + hd;
                *(uint32_t*)&OH[off] = hi;
                *(uint32_t*)&OL[off] = lo;
            }
        }
    }
}

// ---------------------------------------------------------------------------
// V projection: uniform fp16 epilogue. grid.x=8
// ---------------------------------------------------------------------------
__global__ __launch_bounds__(256, 2) void v_gemm_mma()
{
    extern __shared__ char sm[];
    const int nb = blockIdx.x * 128;
    const int m0 = blockIdx.y * 128;

    float acc[4][4][4];
    gemm_mainloop(g_xh, g_wh[2], g_wl[2], m0, nb, sm, acc);

    const int tid = threadIdx.x, wid = tid >> 5, lane = tid & 31;
    const int wm = (wid >> 2) * 64, wn = (wid & 3) * 32;
    const int gid = lane >> 2, qid = lane & 3;

    #pragma unroll
    for (int t = 0; t < 4; t++) {
        #pragma unroll
        for (int n = 0; n < 4; n++) {
            int cc = nb + wn + n*8 + qid*2;
            int h = cc >> 6, hd = cc & 63;
            #pragma unroll
            for (int half = 0; half < 2; half++) {
                int row = m0 + wm + t*16 + gid + 8*half;
                int b = row >> 11, s = row & 2047;
                size_t off = (((size_t)(b*NH + h))*SB + s)*HDIM + hd;
                *(uint32_t*)&g_vh[off] = packh2(acc[t][n][2*half],
                                                acc[t][n][2*half+1]);
            }
        }
    }
}

// ---------------------------------------------------------------------------
// Output projection: out = ctx @ Wo^T + bo (fp32 out)
// ---------------------------------------------------------------------------
__global__ __launch_bounds__(256, 2) void out_gemm_mma(
    const float* __restrict__ bo, float* __restrict__ OUT)
{
    extern __shared__ char sm[];
    const int n0 = blockIdx.x * 128;
    const int m0 = blockIdx.y * 128;

    float acc[4][4][4];
    gemm_mainloop(g_ch, g_wh[3], g_wl[3], m0, n0, sm, acc);

    const int tid = threadIdx.x, wid = tid >> 5, lane = tid & 31;
    const int wm = (wid >> 2) * 64, wn = (wid & 3) * 32;
    const int gid = lane >> 2, qid = lane & 3;

    #pragma unroll
    for (int t = 0; t < 4; t++) {
        #pragma unroll
        for (int n = 0; n < 4; n++) {
            int cn = n0 + wn + n*8 + qid*2;
            float2 bb = *(const float2*)&bo[cn];
            #pragma unroll
            for (int half = 0; half < 2; half++) {
                int row = m0 + wm + t*16 + gid + 8*half;
                float2 v = make_float2(acc[t][n][2*half] + bb.x,
                                       acc[t][n][2*half + 1] + bb.y);
                *(float2*)&OUT[(size_t)row * DD + cn] = v;
            }
        }
    }
}

// ===========================================================================
// Flash attention: QK 3-term bf16, PV single fp16 (P fp16, V fp16).
// Q fragments direct from gmem. 3 KV stages (Kh, Kl bf16 + V fp16), wait1.
// Per-warp skip of fully-masked K-blocks; mask int-math only on diag steps.
// ===========================================================================
#define FP_B  144                    // smem pitch bytes (72 halves)
#define BUF_B  (64*FP_B)             // 9216
#define STG_B  (3*BUF_B)             // 27648
#define FA_SMEM (3*STG_B)            // 82944
#define SCL2  0.18033688f            // 0.125 * log2(e)

__global__ __launch_bounds__(256, 2) void flash_attn_mma()
{
    extern __shared__ char smc[];
    const uint32_t smb = smem_u32(smc);

    const int qt = (int)gridDim.x - 1 - (int)blockIdx.x;   // heavy first
    const int bh = blockIdx.y;
    const int q0 = qt * 128;

    const int tid = threadIdx.x, w = tid >> 5, lane = tid & 31;
    const int wm = w * 16;

    const __nv_bfloat16* Qph = g_qhi + ((size_t)bh*SB + q0)*HDIM;
    const __nv_bfloat16* Qpl = g_qlo + ((size_t)bh*SB + q0)*HDIM;
    const __nv_bfloat16* Kph = g_khi + (size_t)bh*SB*HDIM;
    const __nv_bfloat16* Kpl = g_klo + (size_t)bh*SB*HDIM;
    const __half*        Vp  = g_vh  + (size_t)bh*SB*HDIM;

    auto load_kv = [&](int st, int c0) {
        uint32_t base = smb + st*STG_B;
        for (int idx = tid; idx < 1536; idx += 256) {
            int buf = idx >> 9, r = (idx >> 3) & 63, c = idx & 7;
            const char* sp;
            if (buf == 0)      sp = (const char*)(Kph + (size_t)(c0 + r)*64 + c*8);
            else if (buf == 1) sp = (const char*)(Kpl + (size_t)(c0 + r)*64 + c*8);
            else               sp = (const char*)(Vp  + (size_t)(c0 + r)*64 + c*8);
            cp16(base + buf*BUF_B + r*FP_B + c*16, sp);
        }
    };

    const int nsteps = 2*(qt + 1);
    load_kv(0, 0);  CP_COMMIT;
    load_kv(1, 64); CP_COMMIT;

    // ---- Q fragments: direct gmem loads (A-frag lane map, 4B each) ----
    const int g  = lane >> 2;
    const int q2 = (lane & 3) * 2;
    uint32_t qa[2][4][4];
    #pragma unroll
    for (int term = 0; term < 2; term++) {
        const __nv_bfloat16* Qp = term ? Qpl : Qph;
        #pragma unroll
        for (int kc = 0; kc < 4; kc++)
            #pragma unroll
            for (int rr = 0; rr < 4; rr++) {
                int row = wm + g + ((rr & 1) << 3);
                int col = kc*16 + q2 + ((rr >> 1) << 3);
                qa[term][kc][rr] = *(const uint32_t*)(Qp + (size_t)row*HDIM + col);
            }
    }

    float m0v = -INFINITY, m1v = -INFINITY, l0v = 0.0f, l1v = 0.0f;
    float oc[8][4];
    #pragma unroll
    for (int j = 0; j < 8; j++)
        #pragma unroll
        for (int e = 0; e < 4; e++) oc[j][e] = 0.0f;

    const int brow = (lane & 7) + ((lane >> 4) << 3);
    const int bkk  = ((lane >> 3) & 1) << 3;
    const int vrow = (lane & 7) + (((lane >> 3) & 1) << 3);
    const int vc8  = (lane >> 4) << 3;
    const int r0   = q0 + wm + (lane >> 2);
    const int rmax = q0 + wm + 15;         // last row this warp owns

    int stage = 0;
    for (int kt = 0; kt < nsteps; kt++) {
        const int c0 = kt * 64;
        CP_WAIT1;
        __syncthreads();
        if (kt + 2 < nsteps) {
            int st2 = stage + 2; if (st2 >= 3) st2 -= 3;
            load_kv(st2, (kt + 2)*64);
            CP_COMMIT;
        }

        // Fully-masked block for this warp -> nothing to do (barriers only).
        if (c0 > rmax) { if (++stage == 3) stage = 0; continue; }

        const uint32_t sKh = smb + stage*STG_B;
        const uint32_t sKl = sKh + BUF_B;
        const uint32_t sV  = sKh + 2*BUF_B;

        // ---- S = Q K^T (3-term bf16) ----
        float sc[8][4];
        #pragma unroll
        for (int j = 0; j < 8; j++)
            #pragma unroll
            for (int e = 0; e < 4; e++) sc[j][e] = 0.0f;

        #pragma unroll
        for (int k16 = 0; k16 < 4; k16++) {
            uint32_t kh[8][2], kl[8][2];
            #pragma unroll
            for (int j2 = 0; j2 < 4; j2++) {
                uint32_t off = (uint32_t)((j2*16 + brow)*FP_B + (k16*16 + bkk)*2);
                uint32_t r4[4];
                ldsm4(r4, sKh + off);
                kh[2*j2][0] = r4[0]; kh[2*j2][1] = r4[1];
                kh[2*j2+1][0] = r4[2]; kh[2*j2+1][1] = r4[3];
                ldsm4(r4, sKl + off);
                kl[2*j2][0] = r4[0]; kl[2*j2][1] = r4[1];
                kl[2*j2+1][0] = r4[2]; kl[2*j2+1][1] = r4[3];
            }
            #pragma unroll
            for (int j = 0; j < 8; j++) mma16816(sc[j], qa[0][k16], kh[j]);
            #pragma unroll
            for (int j = 0; j < 8; j++) mma16816(sc[j], qa[0][k16], kl[j]);
            #pragma unroll
            for (int j = 0; j < 8; j++) mma16816(sc[j], qa[1][k16], kh[j]);
        }

        // ---- scale (log2 domain); mask only on boundary blocks ----
        if (c0 + 64 > q0 + wm) {          // block crosses/touches the diagonal
            #pragma unroll
            for (int j = 0; j < 8; j++) {
                int cb = c0 + j*8 + (lane & 3)*2;
                #pragma unroll
                for (int e = 0; e < 4; e++) {
                    float v = sc[j][e] * SCL2;
                    int col = cb + (e & 1);
                    int row = r0 + ((e >> 1) << 3);
                    if (col > row) v = -INFINITY;
                    sc[j][e] = v;
                }
            }
        } else {
            #pragma unroll
            for (int j = 0; j < 8; j++)
                #pragma unroll
                for (int e = 0; e < 4; e++)
                    sc[j][e] *= SCL2;
        }

        // ---- online softmax (base-2) ----
        float mx0 = sc[0][0], mx1 = sc[0][2];
        #pragma unroll
        for (int j = 0; j < 8; j++) {
            mx0 = fmaxf(mx0, fmaxf(sc[j][0], sc[j][1]));
            mx1 = fmaxf(mx1, fmaxf(sc[j][2], sc[j][3]));
        }
        mx0 = fmaxf(mx0, __shfl_xor_sync(0xffffffffu, mx0, 1));
        mx0 = fmaxf(mx0, __shfl_xor_sync(0xffffffffu, mx0, 2));
        mx1 = fmaxf(mx1, __shfl_xor_sync(0xffffffffu, mx1, 1));
        mx1 = fmaxf(mx1, __shfl_xor_sync(0xffffffffu, mx1, 2));

        float mn0 = fmaxf(m0v, mx0), mn1 = fmaxf(m1v, mx1);
        float al0 = exp2f(m0v - mn0), al1 = exp2f(m1v - mn1);
        m0v = mn0; m1v = mn1;

        float s0 = 0.0f, s1 = 0.0f;
        #pragma unroll
        for (int j = 0; j < 8; j++) {
            sc[j][0] = exp2f(sc[j][0] - mn0); s0 += sc[j][0];
            sc[j][1] = exp2f(sc[j][1] - mn0); s0 += sc[j][1];
            sc[j][2] = exp2f(sc[j][2] - mn1); s1 += sc[j][2];
            sc[j][3] = exp2f(sc[j][3] - mn1); s1 += sc[j][3];
        }
        s0 += __shfl_xor_sync(0xffffffffu, s0, 1);
        s0 += __shfl_xor_sync(0xffffffffu, s0, 2);
        s1 += __shfl_xor_sync(0xffffffffu, s1, 1);
        s1 += __shfl_xor_sync(0xffffffffu, s1, 2);
        l0v = l0v * al0 + s0;
        l1v = l1v * al1 + s1;
        #pragma unroll
        for (int j = 0; j < 8; j++) {
            oc[j][0] *= al0; oc[j][1] *= al0;
            oc[j][2] *= al1; oc[j][3] *= al1;
        }

        // ---- pack P to fp16 single (C-frag == A-frag layout) ----
        uint32_t pa[4][4];
        #pragma unroll
        for (int t = 0; t < 4; t++) {
            pa[t][0] = packh2(sc[2*t][0],   sc[2*t][1]);
            pa[t][1] = packh2(sc[2*t][2],   sc[2*t][3]);
            pa[t][2] = packh2(sc[2*t+1][0], sc[2*t+1][1]);
            pa[t][3] = packh2(sc[2*t+1][2], sc[2*t+1][3]);
        }

        // ---- O += P V (single-term fp16) ----
        #pragma unroll
        for (int k16 = 0; k16 < 4; k16++) {
            uint32_t vv[8][2];
            #pragma unroll
            for (int n16 = 0; n16 < 4; n16++) {
                uint32_t off = (uint32_t)((k16*16 + vrow)*FP_B + (n16*16 + vc8)*2);
                uint32_t r4[4];
                ldsm4t(r4, sV + off);
                vv[2*n16][0] = r4[0]; vv[2*n16][1] = r4[1];
                vv[2*n16+1][0] = r4[2]; vv[2*n16+1][1] = r4[3];
            }
            #pragma unroll
            for (int j = 0; j < 8; j++) mma16816h(oc[j], pa[k16], vv[j]);
        }

        if (++stage == 3) stage = 0;
    }

    // ---- finalize, write ctx as fp16 (out_gemm A operand) ----
    const float inv0 = 1.0f / l0v, inv1 = 1.0f / l1v;
    const int b = bh / NH, h = bh % NH;
    const int row0 = q0 + wm + (lane >> 2);
    #pragma unroll
    for (int j = 0; j < 8; j++) {
        int col = h*64 + j*8 + (lane & 3)*2;
        size_t off0 = ((size_t)(b*SB + row0))*DD + col;
        *(uint32_t*)&g_ch[off0] = packh2(oc[j][0]*inv0, oc[j][1]*inv0);
        size_t off1 = ((size_t)(b*SB + row0 + 8))*DD + col;
        *(uint32_t*)&g_ch[off1] = packh2(oc[j][2]*inv1, oc[j][3]*inv1);
    }
}

// ---------------------------------------------------------------------------
extern "C" void kernel_launch(void* const* d_in, const int* in_sizes, int n_in,
                              void* d_out, int out_size)
{
    const float* x  = (const float*)d_in[0];
    const float* Wq = (const float*)d_in[1];
    const float* Wk = (const float*)d_in[2];
    const float* Wv = (const float*)d_in[3];
    const float* Wo = (const float*)d_in[4];
    const float* bo = (const float*)d_in[5];
    float* out = (float*)d_out;

    cudaFuncSetAttribute(qk_gemm_mma,    cudaFuncAttributeMaxDynamicSharedMemorySize, GSMEM);
    cudaFuncSetAttribute(v_gemm_mma,     cudaFuncAttributeMaxDynamicSharedMemorySize, GSMEM);
    cudaFuncSetAttribute(out_gemm_mma,   cudaFuncAttributeMaxDynamicSharedMemorySize, GSMEM);
    cudaFuncSetAttribute(flash_attn_mma, cudaFuncAttributeMaxDynamicSharedMemorySize, FA_SMEM);

    convert_all<<<dim3(160, 5), 256>>>(x, Wq, Wk, Wv, Wo);
    qk_gemm_mma<<<dim3(16, 32), 256, GSMEM>>>();
    v_gemm_mma<<<dim3(8, 32), 256, GSMEM>>>();
    flash_attn_mma<<<dim3(SB/128, BB*NH), 256, FA_SMEM>>>();
    out_gemm_mma<<<dim3(8, 32), 256, GSMEM>>>(bo, out);
}

// round 15
// speedup vs baseline: 1.7240x; 1.7240x over previous
#include <cuda_runtime.h>
#include <cuda_fp16.h>
#include <math.h>
#include <stdint.h>

// Problem constants
#define SB   2048
#define BB   2
#define DD   1024
#define NH   16
#define HDIM 64
#define MR   (BB*SB)       // 4096

// Scratch (device globals) — everything fp16 now
__device__ __align__(256) __half g_xh[(size_t)MR*DD];
__device__ __align__(256) __half g_wh[4][(size_t)DD*DD];
__device__ __align__(256) __half g_wl[4][(size_t)DD*DD];
__device__ __align__(256) __half g_ch[(size_t)MR*DD];          // ctx fp16
__device__ __align__(256) __half g_qh[(size_t)MR*DD];          // Q hi  [b,h,s,hd]
__device__ __align__(256) __half g_ql[(size_t)MR*DD];          // Q lo
__device__ __align__(256) __half g_kh[(size_t)MR*DD];          // K single
__device__ __align__(256) __half g_vh[(size_t)MR*DD];          // V single

// ===========================================================================
// Helpers
// ===========================================================================
__device__ __forceinline__ uint32_t smem_u32(const void* p) {
    uint32_t a;
    asm("{ .reg .u64 t; cvta.to.shared.u64 t, %1; cvt.u32.u64 %0, t; }"
        : "=r"(a) : "l"(p));
    return a;
}

__device__ __forceinline__ void ldsm4(uint32_t* r, uint32_t a) {
    asm volatile("ldmatrix.sync.aligned.m8n8.x4.shared.b16 {%0,%1,%2,%3}, [%4];"
                 : "=r"(r[0]), "=r"(r[1]), "=r"(r[2]), "=r"(r[3]) : "r"(a));
}

__device__ __forceinline__ void ldsm4t(uint32_t* r, uint32_t a) {
    asm volatile("ldmatrix.sync.aligned.m8n8.x4.trans.shared.b16 {%0,%1,%2,%3}, [%4];"
                 : "=r"(r[0]), "=r"(r[1]), "=r"(r[2]), "=r"(r[3]) : "r"(a));
}

__device__ __forceinline__ void mma16816h(float* c, const uint32_t* a, const uint32_t* b) {
    asm volatile(
        "mma.sync.aligned.m16n8k16.row.col.f32.f16.f16.f32 "
        "{%0,%1,%2,%3}, {%4,%5,%6,%7}, {%8,%9}, {%0,%1,%2,%3};"
        : "+f"(c[0]), "+f"(c[1]), "+f"(c[2]), "+f"(c[3])
        : "r"(a[0]), "r"(a[1]), "r"(a[2]), "r"(a[3]), "r"(b[0]), "r"(b[1]));
}

__device__ __forceinline__ void cp16(uint32_t dst, const void* src) {
    asm volatile("cp.async.cg.shared.global [%0], [%1], 16;"
                 :: "r"(dst), "l"(src) : "memory");
}
#define CP_COMMIT asm volatile("cp.async.commit_group;" ::: "memory")
#define CP_WAIT1  asm volatile("cp.async.wait_group 1;"  ::: "memory")

__device__ __forceinline__ uint32_t packsplit_h(float a, float b, uint32_t& lo) {
    __half ha = __float2half_rn(a), hb = __float2half_rn(b);
    __half2 l = __halves2half2(__float2half_rn(a - __half2float(ha)),
                               __float2half_rn(b - __half2float(hb)));
    lo = *(uint32_t*)&l;
    __half2 h = __halves2half2(ha, hb);
    return *(uint32_t*)&h;
}

__device__ __forceinline__ uint32_t packh2(float a, float b) {
    __half2 h = __floats2half2_rn(a, b);
    return *(uint32_t*)&h;
}

// ===========================================================================
// Convert: x -> fp16 single; W -> fp16 hi+lo. One launch, 5 segments.
// ===========================================================================
__global__ void convert_all(const float* __restrict__ x,
                            const float* __restrict__ Wq,
                            const float* __restrict__ Wk,
                            const float* __restrict__ Wv,
                            const float* __restrict__ Wo)
{
    const int seg = blockIdx.y;
    if (seg == 0) {
        int n4 = MR*DD/4;
        for (int i = blockIdx.x * blockDim.x + threadIdx.x; i < n4;
             i += gridDim.x * blockDim.x) {
            float4 v = ((const float4*)x)[i];
            ((uint2*)g_xh)[i] = make_uint2(packh2(v.x, v.y), packh2(v.z, v.w));
        }
        return;
    }
    const float* src = (seg == 1) ? Wq : (seg == 2) ? Wk : (seg == 3) ? Wv : Wo;
    __half* hi = g_wh[seg-1];
    __half* lo = g_wl[seg-1];
    int n4 = DD*DD/4;
    for (int i = blockIdx.x * blockDim.x + threadIdx.x; i < n4;
         i += gridDim.x * blockDim.x) {
        float4 v = ((const float4*)src)[i];
        uint32_t l01, l23;
        uint32_t h01 = packsplit_h(v.x, v.y, l01);
        uint32_t h23 = packsplit_h(v.z, v.w, l23);
        ((uint2*)hi)[i] = make_uint2(h01, h23);
        ((uint2*)lo)[i] = make_uint2(l01, l23);
    }
}

// ===========================================================================
// fp16 2-term GEMM mainloop (round-9/10 proven): K-step 32, 3 stages, wait1,
// XOR-swizzled 64B-pitch tiles. Stage = 3 tiles (A, Bh, Bl).
// ===========================================================================
#define GP_B        64
#define TILE_B      (128*GP_B)          // 8192
#define STAGE_B     (3*TILE_B)          // 24576
#define GSMEM       (3*STAGE_B)         // 73728

__device__ __forceinline__ uint32_t gsw(int row, int chunk) {
    return (uint32_t)(row * GP_B + ((chunk ^ ((row >> 1) & 3)) << 4));
}

__device__ __forceinline__ void gemm_mainloop(
    const __half* __restrict__ A,
    const __half* __restrict__ Bh, const __half* __restrict__ Bl,
    int m0, int n0, char* sm, float acc[4][4][4])
{
    const int tid = threadIdx.x;
    const uint32_t smb = smem_u32(sm);

    #pragma unroll
    for (int t = 0; t < 4; t++)
        #pragma unroll
        for (int n = 0; n < 4; n++)
            #pragma unroll
            for (int e = 0; e < 4; e++) acc[t][n][e] = 0.0f;

    auto load_stage = [&](int st, int k0) {
        uint32_t base = smb + st * STAGE_B;
        #pragma unroll
        for (int j = 0; j < 2; j++) {
            int idx = tid + j * 256;
            int r = idx >> 2, c = idx & 3;
            uint32_t doff = gsw(r, c);
            size_t sa = (size_t)(m0 + r) * DD + k0 + c * 8;
            size_t sb = (size_t)(n0 + r) * DD + k0 + c * 8;
            cp16(base + doff,            A  + sa);
            cp16(base + TILE_B + doff,   Bh + sb);
            cp16(base + 2*TILE_B + doff, Bl + sb);
        }
    };

    load_stage(0, 0);  CP_COMMIT;
    load_stage(1, 32); CP_COMMIT;

    const int wid = tid >> 5, lane = tid & 31;
    const int wm = (wid >> 2) * 64;
    const int wn = (wid & 3) * 32;
    const int arow = lane & 15;
    const int ack  = lane >> 4;
    const int brow = (lane & 7) + ((lane >> 4) << 3);
    const int bck  = (lane >> 3) & 1;

    int stage = 0;
    for (int kt = 0; kt < 32; kt++) {
        CP_WAIT1;
        __syncthreads();
        if (kt + 2 < 32) {
            int st2 = stage + 2; if (st2 >= 3) st2 -= 3;
            load_stage(st2, (kt + 2) * 32);
            CP_COMMIT;
        }

        uint32_t base = smb + stage * STAGE_B;
        uint32_t sA = base, sBh = base + TILE_B, sBl = base + 2*TILE_B;

        #pragma unroll
        for (int k16 = 0; k16 < 2; k16++) {
            uint32_t ah[4][4], bh[4][2], bl[4][2];
            #pragma unroll
            for (int t = 0; t < 4; t++)
                ldsm4(ah[t], sA + gsw(wm + t*16 + arow, k16*2 + ack));
            #pragma unroll
            for (int p = 0; p < 2; p++) {
                uint32_t bo = gsw(wn + p*16 + brow, k16*2 + bck);
                uint32_t r4[4];
                ldsm4(r4, sBh + bo);
                bh[2*p][0] = r4[0]; bh[2*p][1] = r4[1];
                bh[2*p+1][0] = r4[2]; bh[2*p+1][1] = r4[3];
                ldsm4(r4, sBl + bo);
                bl[2*p][0] = r4[0]; bl[2*p][1] = r4[1];
                bl[2*p+1][0] = r4[2]; bl[2*p+1][1] = r4[3];
            }
            #pragma unroll
            for (int t = 0; t < 4; t++)
                #pragma unroll
                for (int n = 0; n < 4; n++)
                    mma16816h(acc[t][n], ah[t], bh[n]);
            #pragma unroll
            for (int t = 0; t < 4; t++)
                #pragma unroll
                for (int n = 0; n < 4; n++)
                    mma16816h(acc[t][n], ah[t], bl[n]);
        }

        if (++stage == 3) stage = 0;
    }
}

// ---------------------------------------------------------------------------
// Q projection: fp16 hi/lo epilogue. grid.x=8
// ---------------------------------------------------------------------------
__global__ __launch_bounds__(256, 2) void q_gemm_mma()
{
    extern __shared__ char sm[];
    const int nb = blockIdx.x * 128;
    const int m0 = blockIdx.y * 128;

    float acc[4][4][4];
    gemm_mainloop(g_xh, g_wh[0], g_wl[0], m0, nb, sm, acc);

    const int tid = threadIdx.x, wid = tid >> 5, lane = tid & 31;
    const int wm = (wid >> 2) * 64, wn = (wid & 3) * 32;
    const int gid = lane >> 2, qid = lane & 3;

    #pragma unroll
    for (int t = 0; t < 4; t++) {
        #pragma unroll
        for (int n = 0; n < 4; n++) {
            int cc = nb + wn + n*8 + qid*2;
            int h = cc >> 6, hd = cc & 63;
            #pragma unroll
            for (int half = 0; half < 2; half++) {
                int row = m0 + wm + t*16 + gid + 8*half;
                int b = row >> 11, s = row & 2047;
                uint32_t lo;
                uint32_t hi = packsplit_h(acc[t][n][2*half], acc[t][n][2*half+1], lo);
                size_t off = (((size_t)(b*NH + h))*SB + s)*HDIM + hd;
                *(uint32_t*)&g_qh[off] = hi;
                *(uint32_t*)&g_ql[off] = lo;
            }
        }
    }
}

// ---------------------------------------------------------------------------
// K/V projection: uniform fp16-single epilogue. grid.x=16 (k:0-7, v:8-15)
// ---------------------------------------------------------------------------
__global__ __launch_bounds__(256, 2) void kv_gemm_mma()
{
    extern __shared__ char sm[];
    const int which = blockIdx.x >> 3;      // 0=k, 1=v
    const int nb = (blockIdx.x & 7) * 128;
    const int m0 = blockIdx.y * 128;

    __half* OUT = which ? g_vh : g_kh;

    float acc[4][4][4];
    gemm_mainloop(g_xh, g_wh[1 + which], g_wl[1 + which], m0, nb, sm, acc);

    const int tid = threadIdx.x, wid = tid >> 5, lane = tid & 31;
    const int wm = (wid >> 2) * 64, wn = (wid & 3) * 32;
    const int gid = lane >> 2, qid = lane & 3;

    #pragma unroll
    for (int t = 0; t < 4; t++) {
        #pragma unroll
        for (int n = 0; n < 4; n++) {
            int cc = nb + wn + n*8 + qid*2;
            int h = cc >> 6, hd = cc & 63;
            #pragma unroll
            for (int half = 0; half < 2; half++) {
                int row = m0 + wm + t*16 + gid + 8*half;
                int b = row >> 11, s = row & 2047;
                size_t off = (((size_t)(b*NH + h))*SB + s)*HDIM + hd;
                *(uint32_t*)&OUT[off] = packh2(acc[t][n][2*half],
                                               acc[t][n][2*half+1]);
            }
        }
    }
}

// ---------------------------------------------------------------------------
// Output projection: out = ctx @ Wo^T + bo (fp32 out)
// ---------------------------------------------------------------------------
__global__ __launch_bounds__(256, 2) void out_gemm_mma(
    const float* __restrict__ bo, float* __restrict__ OUT)
{
    extern __shared__ char sm[];
    const int n0 = blockIdx.x * 128;
    const int m0 = blockIdx.y * 128;

    float acc[4][4][4];
    gemm_mainloop(g_ch, g_wh[3], g_wl[3], m0, n0, sm, acc);

    const int tid = threadIdx.x, wid = tid >> 5, lane = tid & 31;
    const int wm = (wid >> 2) * 64, wn = (wid & 3) * 32;
    const int gid = lane >> 2, qid = lane & 3;

    #pragma unroll
    for (int t = 0; t < 4; t++) {
        #pragma unroll
        for (int n = 0; n < 4; n++) {
            int cn = n0 + wn + n*8 + qid*2;
            float2 bb = *(const float2*)&bo[cn];
            #pragma unroll
            for (int half = 0; half < 2; half++) {
                int row = m0 + wm + t*16 + gid + 8*half;
                float2 v = make_float2(acc[t][n][2*half] + bb.x,
                                       acc[t][n][2*half + 1] + bb.y);
                *(float2*)&OUT[(size_t)row * DD + cn] = v;
            }
        }
    }
}

// ===========================================================================
// Flash attention, all-fp16 MMAs:
//   QK: 2-term (Q hi/lo fp16 from gmem, K single fp16) -> 64 MMAs/step
//   PV: single fp16                                    -> 32 MMAs/step
// 3 KV stages of (K fp16 + V fp16) = 18432 B each, wait1, prefetch 2 ahead.
// Per-warp skip of fully-masked blocks; mask math only on diagonal blocks.
// ===========================================================================
#define FP_B  144                    // smem pitch bytes (72 halves)
#define BUF_B  (64*FP_B)             // 9216
#define STG_B  (2*BUF_B)             // 18432
#define FA_SMEM (3*STG_B)            // 55296
#define SCL2  0.18033688f            // 0.125 * log2(e)

__global__ __launch_bounds__(256, 2) void flash_attn_mma()
{
    extern __shared__ char smc[];
    const uint32_t smb = smem_u32(smc);

    const int qt = (int)gridDim.x - 1 - (int)blockIdx.x;   // heavy first
    const int bh = blockIdx.y;
    const int q0 = qt * 128;

    const int tid = threadIdx.x, w = tid >> 5, lane = tid & 31;
    const int wm = w * 16;

    const __half* Qph = g_qh + ((size_t)bh*SB + q0)*HDIM;
    const __half* Qpl = g_ql + ((size_t)bh*SB + q0)*HDIM;
    const __half* Kp  = g_kh + (size_t)bh*SB*HDIM;
    const __half* Vp  = g_vh + (size_t)bh*SB*HDIM;

    auto load_kv = [&](int st, int c0) {
        uint32_t base = smb + st*STG_B;
        for (int idx = tid; idx < 1024; idx += 256) {
            int buf = idx >> 9, r = (idx >> 3) & 63, c = idx & 7;
            const __half* sp = (buf ? Vp : Kp) + (size_t)(c0 + r)*64 + c*8;
            cp16(base + buf*BUF_B + r*FP_B + c*16, sp);
        }
    };

    const int nsteps = 2*(qt + 1);
    load_kv(0, 0);  CP_COMMIT;
    load_kv(1, 64); CP_COMMIT;

    // ---- Q fragments: direct gmem loads (A-frag lane map, 4B each) ----
    const int g  = lane >> 2;
    const int q2 = (lane & 3) * 2;
    uint32_t qa[2][4][4];
    #pragma unroll
    for (int term = 0; term < 2; term++) {
        const __half* Qp = term ? Qpl : Qph;
        #pragma unroll
        for (int kc = 0; kc < 4; kc++)
            #pragma unroll
            for (int rr = 0; rr < 4; rr++) {
                int row = wm + g + ((rr & 1) << 3);
                int col = kc*16 + q2 + ((rr >> 1) << 3);
                qa[term][kc][rr] = *(const uint32_t*)(Qp + (size_t)row*HDIM + col);
            }
    }

    float m0v = -INFINITY, m1v = -INFINITY, l0v = 0.0f, l1v = 0.0f;
    float oc[8][4];
    #pragma unroll
    for (int j = 0; j < 8; j++)
        #pragma unroll
        for (int e = 0; e < 4; e++) oc[j][e] = 0.0f;

    const int brow = (lane & 7) + ((lane >> 4) << 3);
    const int bkk  = ((lane >> 3) & 1) << 3;
    const int vrow = (lane & 7) + (((lane >> 3) & 1) << 3);
    const int vc8  = (lane >> 4) << 3;
    const int r0   = q0 + wm + (lane >> 2);
    const int rmax = q0 + wm + 15;         // last row this warp owns

    int stage = 0;
    for (int kt = 0; kt < nsteps; kt++) {
        const int c0 = kt * 64;
        CP_WAIT1;
        __syncthreads();
        if (kt + 2 < nsteps) {
            int st2 = stage + 2; if (st2 >= 3) st2 -= 3;
            load_kv(st2, (kt + 2)*64);
            CP_COMMIT;
        }

        // Fully-masked block for this warp -> nothing to do (barriers only).
        if (c0 > rmax) { if (++stage == 3) stage = 0; continue; }

        const uint32_t sK = smb + stage*STG_B;
        const uint32_t sV = sK + BUF_B;

        // ---- S = Q K^T (2-term fp16: Q hi/lo, K single) ----
        float sc[8][4];
        #pragma unroll
        for (int j = 0; j < 8; j++)
            #pragma unroll
            for (int e = 0; e < 4; e++) sc[j][e] = 0.0f;

        #pragma unroll
        for (int k16 = 0; k16 < 4; k16++) {
            uint32_t kk[8][2];
            #pragma unroll
            for (int j2 = 0; j2 < 4; j2++) {
                uint32_t off = (uint32_t)((j2*16 + brow)*FP_B + (k16*16 + bkk)*2);
                uint32_t r4[4];
                ldsm4(r4, sK + off);
                kk[2*j2][0] = r4[0]; kk[2*j2][1] = r4[1];
                kk[2*j2+1][0] = r4[2]; kk[2*j2+1][1] = r4[3];
            }
            #pragma unroll
            for (int j = 0; j < 8; j++) mma16816h(sc[j], qa[0][k16], kk[j]);
            #pragma unroll
            for (int j = 0; j < 8; j++) mma16816h(sc[j], qa[1][k16], kk[j]);
        }

        // ---- scale (log2 domain); mask only on boundary blocks ----
        if (c0 + 64 > q0 + wm) {          // block crosses/touches the diagonal
            #pragma unroll
            for (int j = 0; j < 8; j++) {
                int cb = c0 + j*8 + (lane & 3)*2;
                #pragma unroll
                for (int e = 0; e < 4; e++) {
                    float v = sc[j][e] * SCL2;
                    int col = cb + (e & 1);
                    int row = r0 + ((e >> 1) << 3);
                    if (col > row) v = -INFINITY;
                    sc[j][e] = v;
                }
            }
        } else {
            #pragma unroll
            for (int j = 0; j < 8; j++)
                #pragma unroll
                for (int e = 0; e < 4; e++)
                    sc[j][e] *= SCL2;
        }

        // ---- online softmax (base-2) ----
        float mx0 = sc[0][0], mx1 = sc[0][2];
        #pragma unroll
        for (int j = 0; j < 8; j++) {
            mx0 = fmaxf(mx0, fmaxf(sc[j][0], sc[j][1]));
            mx1 = fmaxf(mx1, fmaxf(sc[j][2], sc[j][3]));
        }
        mx0 = fmaxf(mx0, __shfl_xor_sync(0xffffffffu, mx0, 1));
        mx0 = fmaxf(mx0, __shfl_xor_sync(0xffffffffu, mx0, 2));
        mx1 = fmaxf(mx1, __shfl_xor_sync(0xffffffffu, mx1, 1));
        mx1 = fmaxf(mx1, __shfl_xor_sync(0xffffffffu, mx1, 2));

        float mn0 = fmaxf(m0v, mx0), mn1 = fmaxf(m1v, mx1);
        float al0 = exp2f(m0v - mn0), al1 = exp2f(m1v - mn1);
        m0v = mn0; m1v = mn1;

        float s0 = 0.0f, s1 = 0.0f;
        #pragma unroll
        for (int j = 0; j < 8; j++) {
            sc[j][0] = exp2f(sc[j][0] - mn0); s0 += sc[j][0];
            sc[j][1] = exp2f(sc[j][1] - mn0); s0 += sc[j][1];
            sc[j][2] = exp2f(sc[j][2] - mn1); s1 += sc[j][2];
            sc[j][3] = exp2f(sc[j][3] - mn1); s1 += sc[j][3];
        }
        s0 += __shfl_xor_sync(0xffffffffu, s0, 1);
        s0 += __shfl_xor_sync(0xffffffffu, s0, 2);
        s1 += __shfl_xor_sync(0xffffffffu, s1, 1);
        s1 += __shfl_xor_sync(0xffffffffu, s1, 2);
        l0v = l0v * al0 + s0;
        l1v = l1v * al1 + s1;
        #pragma unroll
        for (int j = 0; j < 8; j++) {
            oc[j][0] *= al0; oc[j][1] *= al0;
            oc[j][2] *= al1; oc[j][3] *= al1;
        }

        // ---- pack P to fp16 single (C-frag == A-frag layout) ----
        uint32_t pa[4][4];
        #pragma unroll
        for (int t = 0; t < 4; t++) {
            pa[t][0] = packh2(sc[2*t][0],   sc[2*t][1]);
            pa[t][1] = packh2(sc[2*t][2],   sc[2*t][3]);
            pa[t][2] = packh2(sc[2*t+1][0], sc[2*t+1][1]);
            pa[t][3] = packh2(sc[2*t+1][2], sc[2*t+1][3]);
        }

        // ---- O += P V (single-term fp16) ----
        #pragma unroll
        for (int k16 = 0; k16 < 4; k16++) {
            uint32_t vv[8][2];
            #pragma unroll
            for (int n16 = 0; n16 < 4; n16++) {
                uint32_t off = (uint32_t)((k16*16 + vrow)*FP_B + (n16*16 + vc8)*2);
                uint32_t r4[4];
                ldsm4t(r4, sV + off);
                vv[2*n16][0] = r4[0]; vv[2*n16][1] = r4[1];
                vv[2*n16+1][0] = r4[2]; vv[2*n16+1][1] = r4[3];
            }
            #pragma unroll
            for (int j = 0; j < 8; j++) mma16816h(oc[j], pa[k16], vv[j]);
        }

        if (++stage == 3) stage = 0;
    }

    // ---- finalize, write ctx as fp16 (out_gemm A operand) ----
    const float inv0 = 1.0f / l0v, inv1 = 1.0f / l1v;
    const int b = bh / NH, h = bh % NH;
    const int row0 = q0 + wm + (lane >> 2);
    #pragma unroll
    for (int j = 0; j < 8; j++) {
        int col = h*64 + j*8 + (lane & 3)*2;
        size_t off0 = ((size_t)(b*SB + row0))*DD + col;
        *(uint32_t*)&g_ch[off0] = packh2(oc[j][0]*inv0, oc[j][1]*inv0);
        size_t off1 = ((size_t)(b*SB + row0 + 8))*DD + col;
        *(uint32_t*)&g_ch[off1] = packh2(oc[j][2]*inv1, oc[j][3]*inv1);
    }
}

// ---------------------------------------------------------------------------
extern "C" void kernel_launch(void* const* d_in, const int* in_sizes, int n_in,
                              void* d_out, int out_size)
{
    const float* x  = (const float*)d_in[0];
    const float* Wq = (const float*)d_in[1];
    const float* Wk = (const float*)d_in[2];
    const float* Wv = (const float*)d_in[3];
    const float* Wo = (const float*)d_in[4];
    const float* bo = (const float*)d_in[5];
    float* out = (float*)d_out;

    cudaFuncSetAttribute(q_gemm_mma,     cudaFuncAttributeMaxDynamicSharedMemorySize, GSMEM);
    cudaFuncSetAttribute(kv_gemm_mma,    cudaFuncAttributeMaxDynamicSharedMemorySize, GSMEM);
    cudaFuncSetAttribute(out_gemm_mma,   cudaFuncAttributeMaxDynamicSharedMemorySize, GSMEM);
    cudaFuncSetAttribute(flash_attn_mma, cudaFuncAttributeMaxDynamicSharedMemorySize, FA_SMEM);

    convert_all<<<dim3(160, 5), 256>>>(x, Wq, Wk, Wv, Wo);
    q_gemm_mma<<<dim3(8, 32), 256, GSMEM>>>();
    kv_gemm_mma<<<dim3(16, 32), 256, GSMEM>>>();
    flash_attn_mma<<<dim3(SB/128, BB*NH), 256, FA_SMEM>>>();
    out_gemm_mma<<<dim3(8, 32), 256, GSMEM>>>(bo, out);
}

// round 16
// speedup vs baseline: 2.2711x; 1.3174x over previous
#include <cuda_runtime.h>
#include <cuda_fp16.h>
#include <math.h>
#include <stdint.h>

// Problem constants
#define SB   2048
#define BB   2
#define DD   1024
#define NH   16
#define HDIM 64
#define MR   (BB*SB)       // 4096

// Scratch (device globals) — everything fp16
__device__ __align__(256) __half g_xh[(size_t)MR*DD];
__device__ __align__(256) __half g_wh[4][(size_t)DD*DD];
__device__ __align__(256) __half g_ch[(size_t)MR*DD];          // ctx fp16
__device__ __align__(256) __half g_qh[(size_t)MR*DD];          // Q hi  [b,h,s,hd]
__device__ __align__(256) __half g_ql[(size_t)MR*DD];          // Q lo
__device__ __align__(256) __half g_kh[(size_t)MR*DD];          // K single
__device__ __align__(256) __half g_vh[(size_t)MR*DD];          // V single

// ===========================================================================
// Helpers
// ===========================================================================
__device__ __forceinline__ uint32_t smem_u32(const void* p) {
    uint32_t a;
    asm("{ .reg .u64 t; cvta.to.shared.u64 t, %1; cvt.u32.u64 %0, t; }"
        : "=r"(a) : "l"(p));
    return a;
}

__device__ __forceinline__ void ldsm4(uint32_t* r, uint32_t a) {
    asm volatile("ldmatrix.sync.aligned.m8n8.x4.shared.b16 {%0,%1,%2,%3}, [%4];"
                 : "=r"(r[0]), "=r"(r[1]), "=r"(r[2]), "=r"(r[3]) : "r"(a));
}

__device__ __forceinline__ void ldsm4t(uint32_t* r, uint32_t a) {
    asm volatile("ldmatrix.sync.aligned.m8n8.x4.trans.shared.b16 {%0,%1,%2,%3}, [%4];"
                 : "=r"(r[0]), "=r"(r[1]), "=r"(r[2]), "=r"(r[3]) : "r"(a));
}

__device__ __forceinline__ void mma16816h(float* c, const uint32_t* a, const uint32_t* b) {
    asm volatile(
        "mma.sync.aligned.m16n8k16.row.col.f32.f16.f16.f32 "
        "{%0,%1,%2,%3}, {%4,%5,%6,%7}, {%8,%9}, {%0,%1,%2,%3};"
        : "+f"(c[0]), "+f"(c[1]), "+f"(c[2]), "+f"(c[3])
        : "r"(a[0]), "r"(a[1]), "r"(a[2]), "r"(a[3]), "r"(b[0]), "r"(b[1]));
}

__device__ __forceinline__ void cp16(uint32_t dst, const void* src) {
    asm volatile("cp.async.cg.shared.global [%0], [%1], 16;"
                 :: "r"(dst), "l"(src) : "memory");
}
#define CP_COMMIT asm volatile("cp.async.commit_group;" ::: "memory")
#define CP_WAIT1  asm volatile("cp.async.wait_group 1;"  ::: "memory")

__device__ __forceinline__ uint32_t packsplit_h(float a, float b, uint32_t& lo) {
    __half ha = __float2half_rn(a), hb = __float2half_rn(b);
    __half2 l = __halves2half2(__float2half_rn(a - __half2float(ha)),
                               __float2half_rn(b - __half2float(hb)));
    lo = *(uint32_t*)&l;
    __half2 h = __halves2half2(ha, hb);
    return *(uint32_t*)&h;
}

__device__ __forceinline__ uint32_t packh2(float a, float b) {
    __half2 h = __floats2half2_rn(a, b);
    return *(uint32_t*)&h;
}

// ===========================================================================
// Convert: x and all W -> fp16 single. One launch, 5 segments.
// ===========================================================================
__global__ void convert_all(const float* __restrict__ x,
                            const float* __restrict__ Wq,
                            const float* __restrict__ Wk,
                            const float* __restrict__ Wv,
                            const float* __restrict__ Wo)
{
    const int seg = blockIdx.y;
    const float* src;
    __half* dst;
    int n4;
    switch (seg) {
        case 0:  src = x;  dst = g_xh;    n4 = MR*DD/4; break;
        case 1:  src = Wq; dst = g_wh[0]; n4 = DD*DD/4; break;
        case 2:  src = Wk; dst = g_wh[1]; n4 = DD*DD/4; break;
        case 3:  src = Wv; dst = g_wh[2]; n4 = DD*DD/4; break;
        default: src = Wo; dst = g_wh[3]; n4 = DD*DD/4; break;
    }
    for (int i = blockIdx.x * blockDim.x + threadIdx.x; i < n4;
         i += gridDim.x * blockDim.x) {
        float4 v = ((const float4*)src)[i];
        ((uint2*)dst)[i] = make_uint2(packh2(v.x, v.y), packh2(v.z, v.w));
    }
}

// ===========================================================================
// Plain fp16 GEMM mainloop: D = A * B^T, K-step 32, 3 stages, wait1,
// XOR-swizzled 64B-pitch tiles. Stage = 2 tiles (A, B). 32 MMAs/iter.
// ===========================================================================
#define GP_B        64
#define TILE_B      (128*GP_B)          // 8192
#define STAGE_B     (2*TILE_B)          // 16384
#define GSMEM       (3*STAGE_B)         // 49152

__device__ __forceinline__ uint32_t gsw(int row, int chunk) {
    return (uint32_t)(row * GP_B + ((chunk ^ ((row >> 1) & 3)) << 4));
}

__device__ __forceinline__ void gemm_mainloop(
    const __half* __restrict__ A, const __half* __restrict__ B,
    int m0, int n0, char* sm, float acc[4][4][4])
{
    const int tid = threadIdx.x;
    const uint32_t smb = smem_u32(sm);

    #pragma unroll
    for (int t = 0; t < 4; t++)
        #pragma unroll
        for (int n = 0; n < 4; n++)
            #pragma unroll
            for (int e = 0; e < 4; e++) acc[t][n][e] = 0.0f;

    auto load_stage = [&](int st, int k0) {
        uint32_t base = smb + st * STAGE_B;
        #pragma unroll
        for (int j = 0; j < 2; j++) {
            int idx = tid + j * 256;
            int r = idx >> 2, c = idx & 3;
            uint32_t doff = gsw(r, c);
            cp16(base + doff,          A + (size_t)(m0 + r) * DD + k0 + c * 8);
            cp16(base + TILE_B + doff, B + (size_t)(n0 + r) * DD + k0 + c * 8);
        }
    };

    load_stage(0, 0);  CP_COMMIT;
    load_stage(1, 32); CP_COMMIT;

    const int wid = tid >> 5, lane = tid & 31;
    const int wm = (wid >> 2) * 64;
    const int wn = (wid & 3) * 32;
    const int arow = lane & 15;
    const int ack  = lane >> 4;
    const int brow = (lane & 7) + ((lane >> 4) << 3);
    const int bck  = (lane >> 3) & 1;

    int stage = 0;
    for (int kt = 0; kt < 32; kt++) {
        CP_WAIT1;
        __syncthreads();
        if (kt + 2 < 32) {
            int st2 = stage + 2; if (st2 >= 3) st2 -= 3;
            load_stage(st2, (kt + 2) * 32);
            CP_COMMIT;
        }

        uint32_t base = smb + stage * STAGE_B;
        uint32_t sA = base, sB = base + TILE_B;

        #pragma unroll
        for (int k16 = 0; k16 < 2; k16++) {
            uint32_t ah[4][4], bh[4][2];
            #pragma unroll
            for (int t = 0; t < 4; t++)
                ldsm4(ah[t], sA + gsw(wm + t*16 + arow, k16*2 + ack));
            #pragma unroll
            for (int p = 0; p < 2; p++) {
                uint32_t bo = gsw(wn + p*16 + brow, k16*2 + bck);
                uint32_t r4[4];
                ldsm4(r4, sB + bo);
                bh[2*p][0] = r4[0]; bh[2*p][1] = r4[1];
                bh[2*p+1][0] = r4[2]; bh[2*p+1][1] = r4[3];
            }
            #pragma unroll
            for (int t = 0; t < 4; t++)
                #pragma unroll
                for (int n = 0; n < 4; n++)
                    mma16816h(acc[t][n], ah[t], bh[n]);
        }

        if (++stage == 3) stage = 0;
    }
}

// ---------------------------------------------------------------------------
// Q projection: fp16 hi/lo epilogue. grid.x=8
// ---------------------------------------------------------------------------
__global__ __launch_bounds__(256, 2) void q_gemm_mma()
{
    extern __shared__ char sm[];
    const int nb = blockIdx.x * 128;
    const int m0 = blockIdx.y * 128;

    float acc[4][4][4];
    gemm_mainloop(g_xh, g_wh[0], m0, nb, sm, acc);

    const int tid = threadIdx.x, wid = tid >> 5, lane = tid & 31;
    const int wm = (wid >> 2) * 64, wn = (wid & 3) * 32;
    const int gid = lane >> 2, qid = lane & 3;

    #pragma unroll
    for (int t = 0; t < 4; t++) {
        #pragma unroll
        for (int n = 0; n < 4; n++) {
            int cc = nb + wn + n*8 + qid*2;
            int h = cc >> 6, hd = cc & 63;
            #pragma unroll
            for (int half = 0; half < 2; half++) {
                int row = m0 + wm + t*16 + gid + 8*half;
                int b = row >> 11, s = row & 2047;
                uint32_t lo;
                uint32_t hi = packsplit_h(acc[t][n][2*half], acc[t][n][2*half+1], lo);
                size_t off = (((size_t)(b*NH + h))*SB + s)*HDIM + hd;
                *(uint32_t*)&g_qh[off] = hi;
                *(uint32_t*)&g_ql[off] = lo;
            }
        }
    }
}

// ---------------------------------------------------------------------------
// K/V projection: uniform fp16-single epilogue. grid.x=16 (k:0-7, v:8-15)
// ---------------------------------------------------------------------------
__global__ __launch_bounds__(256, 2) void kv_gemm_mma()
{
    extern __shared__ char sm[];
    const int which = blockIdx.x >> 3;      // 0=k, 1=v
    const int nb = (blockIdx.x & 7) * 128;
    const int m0 = blockIdx.y * 128;

    __half* OUT = which ? g_vh : g_kh;

    float acc[4][4][4];
    gemm_mainloop(g_xh, g_wh[1 + which], m0, nb, sm, acc);

    const int tid = threadIdx.x, wid = tid >> 5, lane = tid & 31;
    const int wm = (wid >> 2) * 64, wn = (wid & 3) * 32;
    const int gid = lane >> 2, qid = lane & 3;

    #pragma unroll
    for (int t = 0; t < 4; t++) {
        #pragma unroll
        for (int n = 0; n < 4; n++) {
            int cc = nb + wn + n*8 + qid*2;
            int h = cc >> 6, hd = cc & 63;
            #pragma unroll
            for (int half = 0; half < 2; half++) {
                int row = m0 + wm + t*16 + gid + 8*half;
                int b = row >> 11, s = row & 2047;
                size_t off = (((size_t)(b*NH + h))*SB + s)*HDIM + hd;
                *(uint32_t*)&OUT[off] = packh2(acc[t][n][2*half],
                                               acc[t][n][2*half+1]);
            }
        }
    }
}

// ---------------------------------------------------------------------------
// Output projection: out = ctx @ Wo^T + bo (fp32 out)
// ---------------------------------------------------------------------------
__global__ __launch_bounds__(256, 2) void out_gemm_mma(
    const float* __restrict__ bo, float* __restrict__ OUT)
{
    extern __shared__ char sm[];
    const int n0 = blockIdx.x * 128;
    const int m0 = blockIdx.y * 128;

    float acc[4][4][4];
    gemm_mainloop(g_ch, g_wh[3], m0, n0, sm, acc);

    const int tid = threadIdx.x, wid = tid >> 5, lane = tid & 31;
    const int wm = (wid >> 2) * 64, wn = (wid & 3) * 32;
    const int gid = lane >> 2, qid = lane & 3;

    #pragma unroll
    for (int t = 0; t < 4; t++) {
        #pragma unroll
        for (int n = 0; n < 4; n++) {
            int cn = n0 + wn + n*8 + qid*2;
            float2 bb = *(const float2*)&bo[cn];
            #pragma unroll
            for (int half = 0; half < 2; half++) {
                int row = m0 + wm + t*16 + gid + 8*half;
                float2 v = make_float2(acc[t][n][2*half] + bb.x,
                                       acc[t][n][2*half + 1] + bb.y);
                *(float2*)&OUT[(size_t)row * DD + cn] = v;
            }
        }
    }
}

// ===========================================================================
// Flash attention (unchanged from round 15):
//   QK: 2-term (Q hi/lo fp16 from gmem, K single fp16) -> 64 MMAs/step
//   PV: single fp16                                    -> 32 MMAs/step
// 3 KV stages of (K fp16 + V fp16) = 18432 B each, wait1, prefetch 2 ahead.
// ===========================================================================
#define FP_B  144                    // smem pitch bytes (72 halves)
#define BUF_B  (64*FP_B)             // 9216
#define STG_B  (2*BUF_B)             // 18432
#define FA_SMEM (3*STG_B)            // 55296
#define SCL2  0.18033688f            // 0.125 * log2(e)

__global__ __launch_bounds__(256, 2) void flash_attn_mma()
{
    extern __shared__ char smc[];
    const uint32_t smb = smem_u32(smc);

    const int qt = (int)gridDim.x - 1 - (int)blockIdx.x;   // heavy first
    const int bh = blockIdx.y;
    const int q0 = qt * 128;

    const int tid = threadIdx.x, w = tid >> 5, lane = tid & 31;
    const int wm = w * 16;

    const __half* Qph = g_qh + ((size_t)bh*SB + q0)*HDIM;
    const __half* Qpl = g_ql + ((size_t)bh*SB + q0)*HDIM;
    const __half* Kp  = g_kh + (size_t)bh*SB*HDIM;
    const __half* Vp  = g_vh + (size_t)bh*SB*HDIM;

    auto load_kv = [&](int st, int c0) {
        uint32_t base = smb + st*STG_B;
        for (int idx = tid; idx < 1024; idx += 256) {
            int buf = idx >> 9, r = (idx >> 3) & 63, c = idx & 7;
            const __half* sp = (buf ? Vp : Kp) + (size_t)(c0 + r)*64 + c*8;
            cp16(base + buf*BUF_B + r*FP_B + c*16, sp);
        }
    };

    const int nsteps = 2*(qt + 1);
    load_kv(0, 0);  CP_COMMIT;
    load_kv(1, 64); CP_COMMIT;

    // ---- Q fragments: direct gmem loads (A-frag lane map, 4B each) ----
    const int g  = lane >> 2;
    const int q2 = (lane & 3) * 2;
    uint32_t qa[2][4][4];
    #pragma unroll
    for (int term = 0; term < 2; term++) {
        const __half* Qp = term ? Qpl : Qph;
        #pragma unroll
        for (int kc = 0; kc < 4; kc++)
            #pragma unroll
            for (int rr = 0; rr < 4; rr++) {
                int row = wm + g + ((rr & 1) << 3);
                int col = kc*16 + q2 + ((rr >> 1) << 3);
                qa[term][kc][rr] = *(const uint32_t*)(Qp + (size_t)row*HDIM + col);
            }
    }

    float m0v = -INFINITY, m1v = -INFINITY, l0v = 0.0f, l1v = 0.0f;
    float oc[8][4];
    #pragma unroll
    for (int j = 0; j < 8; j++)
        #pragma unroll
        for (int e = 0; e < 4; e++) oc[j][e] = 0.0f;

    const int brow = (lane & 7) + ((lane >> 4) << 3);
    const int bkk  = ((lane >> 3) & 1) << 3;
    const int vrow = (lane & 7) + (((lane >> 3) & 1) << 3);
    const int vc8  = (lane >> 4) << 3;
    const int r0   = q0 + wm + (lane >> 2);
    const int rmax = q0 + wm + 15;         // last row this warp owns

    int stage = 0;
    for (int kt = 0; kt < nsteps; kt++) {
        const int c0 = kt * 64;
        CP_WAIT1;
        __syncthreads();
        if (kt + 2 < nsteps) {
            int st2 = stage + 2; if (st2 >= 3) st2 -= 3;
            load_kv(st2, (kt + 2)*64);
            CP_COMMIT;
        }

        // Fully-masked block for this warp -> nothing to do (barriers only).
        if (c0 > rmax) { if (++stage == 3) stage = 0; continue; }

        const uint32_t sK = smb + stage*STG_B;
        const uint32_t sV = sK + BUF_B;

        // ---- S = Q K^T (2-term fp16: Q hi/lo, K single) ----
        float sc[8][4];
        #pragma unroll
        for (int j = 0; j < 8; j++)
            #pragma unroll
            for (int e = 0; e < 4; e++) sc[j][e] = 0.0f;

        #pragma unroll
        for (int k16 = 0; k16 < 4; k16++) {
            uint32_t kk[8][2];
            #pragma unroll
            for (int j2 = 0; j2 < 4; j2++) {
                uint32_t off = (uint32_t)((j2*16 + brow)*FP_B + (k16*16 + bkk)*2);
                uint32_t r4[4];
                ldsm4(r4, sK + off);
                kk[2*j2][0] = r4[0]; kk[2*j2][1] = r4[1];
                kk[2*j2+1][0] = r4[2]; kk[2*j2+1][1] = r4[3];
            }
            #pragma unroll
            for (int j = 0; j < 8; j++) mma16816h(sc[j], qa[0][k16], kk[j]);
            #pragma unroll
            for (int j = 0; j < 8; j++) mma16816h(sc[j], qa[1][k16], kk[j]);
        }

        // ---- scale (log2 domain); mask only on boundary blocks ----
        if (c0 + 64 > q0 + wm) {          // block crosses/touches the diagonal
            #pragma unroll
            for (int j = 0; j < 8; j++) {
                int cb = c0 + j*8 + (lane & 3)*2;
                #pragma unroll
                for (int e = 0; e < 4; e++) {
                    float v = sc[j][e] * SCL2;
                    int col = cb + (e & 1);
                    int row = r0 + ((e >> 1) << 3);
                    if (col > row) v = -INFINITY;
                    sc[j][e] = v;
                }
            }
        } else {
            #pragma unroll
            for (int j = 0; j < 8; j++)
                #pragma unroll
                for (int e = 0; e < 4; e++)
                    sc[j][e] *= SCL2;
        }

        // ---- online softmax (base-2) ----
        float mx0 = sc[0][0], mx1 = sc[0][2];
        #pragma unroll
        for (int j = 0; j < 8; j++) {
            mx0 = fmaxf(mx0, fmaxf(sc[j][0], sc[j][1]));
            mx1 = fmaxf(mx1, fmaxf(sc[j][2], sc[j][3]));
        }
        mx0 = fmaxf(mx0, __shfl_xor_sync(0xffffffffu, mx0, 1));
        mx0 = fmaxf(mx0, __shfl_xor_sync(0xffffffffu, mx0, 2));
        mx1 = fmaxf(mx1, __shfl_xor_sync(0xffffffffu, mx1, 1));
        mx1 = fmaxf(mx1, __shfl_xor_sync(0xffffffffu, mx1, 2));

        float mn0 = fmaxf(m0v, mx0), mn1 = fmaxf(m1v, mx1);
        float al0 = exp2f(m0v - mn0), al1 = exp2f(m1v - mn1);
        m0v = mn0; m1v = mn1;

        float s0 = 0.0f, s1 = 0.0f;
        #pragma unroll
        for (int j = 0; j < 8; j++) {
            sc[j][0] = exp2f(sc[j][0] - mn0); s0 += sc[j][0];
            sc[j][1] = exp2f(sc[j][1] - mn0); s0 += sc[j][1];
            sc[j][2] = exp2f(sc[j][2] - mn1); s1 += sc[j][2];
            sc[j][3] = exp2f(sc[j][3] - mn1); s1 += sc[j][3];
        }
        s0 += __shfl_xor_sync(0xffffffffu, s0, 1);
        s0 += __shfl_xor_sync(0xffffffffu, s0, 2);
        s1 += __shfl_xor_sync(0xffffffffu, s1, 1);
        s1 += __shfl_xor_sync(0xffffffffu, s1, 2);
        l0v = l0v * al0 + s0;
        l1v = l1v * al1 + s1;
        #pragma unroll
        for (int j = 0; j < 8; j++) {
            oc[j][0] *= al0; oc[j][1] *= al0;
            oc[j][2] *= al1; oc[j][3] *= al1;
        }

        // ---- pack P to fp16 single (C-frag == A-frag layout) ----
        uint32_t pa[4][4];
        #pragma unroll
        for (int t = 0; t < 4; t++) {
            pa[t][0] = packh2(sc[2*t][0],   sc[2*t][1]);
            pa[t][1] = packh2(sc[2*t][2],   sc[2*t][3]);
            pa[t][2] = packh2(sc[2*t+1][0], sc[2*t+1][1]);
            pa[t][3] = packh2(sc[2*t+1][2], sc[2*t+1][3]);
        }

        // ---- O += P V (single-term fp16) ----
        #pragma unroll
        for (int k16 = 0; k16 < 4; k16++) {
            uint32_t vv[8][2];
            #pragma unroll
            for (int n16 = 0; n16 < 4; n16++) {
                uint32_t off = (uint32_t)((k16*16 + vrow)*FP_B + (n16*16 + vc8)*2);
                uint32_t r4[4];
                ldsm4t(r4, sV + off);
                vv[2*n16][0] = r4[0]; vv[2*n16][1] = r4[1];
                vv[2*n16+1][0] = r4[2]; vv[2*n16+1][1] = r4[3];
            }
            #pragma unroll
            for (int j = 0; j < 8; j++) mma16816h(oc[j], pa[k16], vv[j]);
        }

        if (++stage == 3) stage = 0;
    }

    // ---- finalize, write ctx as fp16 (out_gemm A operand) ----
    const float inv0 = 1.0f / l0v, inv1 = 1.0f / l1v;
    const int b = bh / NH, h = bh % NH;
    const int row0 = q0 + wm + (lane >> 2);
    #pragma unroll
    for (int j = 0; j < 8; j++) {
        int col = h*64 + j*8 + (lane & 3)*2;
        size_t off0 = ((size_t)(b*SB + row0))*DD + col;
        *(uint32_t*)&g_ch[off0] = packh2(oc[j][0]*inv0, oc[j][1]*inv0);
        size_t off1 = ((size_t)(b*SB + row0 + 8))*DD + col;
        *(uint32_t*)&g_ch[off1] = packh2(oc[j][2]*inv1, oc[j][3]*inv1);
    }
}

// ---------------------------------------------------------------------------
extern "C" void kernel_launch(void* const* d_in, const int* in_sizes, int n_in,
                              void* d_out, int out_size)
{
    const float* x  = (const float*)d_in[0];
    const float* Wq = (const float*)d_in[1];
    const float* Wk = (const float*)d_in[2];
    const float* Wv = (const float*)d_in[3];
    const float* Wo = (const float*)d_in[4];
    const float* bo = (const float*)d_in[5];
    float* out = (float*)d_out;

    cudaFuncSetAttribute(q_gemm_mma,     cudaFuncAttributeMaxDynamicSharedMemorySize, GSMEM);
    cudaFuncSetAttribute(kv_gemm_mma,    cudaFuncAttributeMaxDynamicSharedMemorySize, GSMEM);
    cudaFuncSetAttribute(out_gemm_mma,   cudaFuncAttributeMaxDynamicSharedMemorySize, GSMEM);
    cudaFuncSetAttribute(flash_attn_mma, cudaFuncAttributeMaxDynamicSharedMemorySize, FA_SMEM);

    convert_all<<<dim3(160, 5), 256>>>(x, Wq, Wk, Wv, Wo);
    q_gemm_mma<<<dim3(8, 32), 256, GSMEM>>>();
    kv_gemm_mma<<<dim3(16, 32), 256, GSMEM>>>();
    flash_attn_mma<<<dim3(SB/128, BB*NH), 256, FA_SMEM>>>();
    out_gemm_mma<<<dim3(8, 32), 256, GSMEM>>>(bo, out);
}

// round 17
// speedup vs baseline: 2.6533x; 1.1683x over previous
#include <cuda_runtime.h>
#include <cuda_fp16.h>
#include <math.h>
#include <stdint.h>

// Problem constants
#define SB   2048
#define BB   2
#define DD   1024
#define NH   16
#define HDIM 64
#define MR   (BB*SB)       // 4096

// Scratch (device globals) — everything fp16 single precision now
__device__ __align__(256) __half g_xh[(size_t)MR*DD];
__device__ __align__(256) __half g_wh[4][(size_t)DD*DD];
__device__ __align__(256) __half g_ch[(size_t)MR*DD];          // ctx fp16
__device__ __align__(256) __half g_qh[(size_t)MR*DD];          // Q [b,h,s,hd]
__device__ __align__(256) __half g_kh[(size_t)MR*DD];          // K
__device__ __align__(256) __half g_vh[(size_t)MR*DD];          // V

// ===========================================================================
// Helpers
// ===========================================================================
__device__ __forceinline__ uint32_t smem_u32(const void* p) {
    uint32_t a;
    asm("{ .reg .u64 t; cvta.to.shared.u64 t, %1; cvt.u32.u64 %0, t; }"
        : "=r"(a) : "l"(p));
    return a;
}

__device__ __forceinline__ void ldsm4(uint32_t* r, uint32_t a) {
    asm volatile("ldmatrix.sync.aligned.m8n8.x4.shared.b16 {%0,%1,%2,%3}, [%4];"
                 : "=r"(r[0]), "=r"(r[1]), "=r"(r[2]), "=r"(r[3]) : "r"(a));
}

__device__ __forceinline__ void ldsm4t(uint32_t* r, uint32_t a) {
    asm volatile("ldmatrix.sync.aligned.m8n8.x4.trans.shared.b16 {%0,%1,%2,%3}, [%4];"
                 : "=r"(r[0]), "=r"(r[1]), "=r"(r[2]), "=r"(r[3]) : "r"(a));
}

__device__ __forceinline__ void mma16816h(float* c, const uint32_t* a, const uint32_t* b) {
    asm volatile(
        "mma.sync.aligned.m16n8k16.row.col.f32.f16.f16.f32 "
        "{%0,%1,%2,%3}, {%4,%5,%6,%7}, {%8,%9}, {%0,%1,%2,%3};"
        : "+f"(c[0]), "+f"(c[1]), "+f"(c[2]), "+f"(c[3])
        : "r"(a[0]), "r"(a[1]), "r"(a[2]), "r"(a[3]), "r"(b[0]), "r"(b[1]));
}

__device__ __forceinline__ void cp16(uint32_t dst, const void* src) {
    asm volatile("cp.async.cg.shared.global [%0], [%1], 16;"
                 :: "r"(dst), "l"(src) : "memory");
}
#define CP_COMMIT asm volatile("cp.async.commit_group;" ::: "memory")
#define CP_WAIT1  asm volatile("cp.async.wait_group 1;"  ::: "memory")

__device__ __forceinline__ uint32_t packh2(float a, float b) {
    __half2 h = __floats2half2_rn(a, b);
    return *(uint32_t*)&h;
}

// ===========================================================================
// Convert: x and all W -> fp16 single. One launch, 5 segments.
// ===========================================================================
__global__ void convert_all(const float* __restrict__ x,
                            const float* __restrict__ Wq,
                            const float* __restrict__ Wk,
                            const float* __restrict__ Wv,
                            const float* __restrict__ Wo)
{
    const int seg = blockIdx.y;
    const float* src;
    __half* dst;
    int n4;
    switch (seg) {
        case 0:  src = x;  dst = g_xh;    n4 = MR*DD/4; break;
        case 1:  src = Wq; dst = g_wh[0]; n4 = DD*DD/4; break;
        case 2:  src = Wk; dst = g_wh[1]; n4 = DD*DD/4; break;
        case 3:  src = Wv; dst = g_wh[2]; n4 = DD*DD/4; break;
        default: src = Wo; dst = g_wh[3]; n4 = DD*DD/4; break;
    }
    for (int i = blockIdx.x * blockDim.x + threadIdx.x; i < n4;
         i += gridDim.x * blockDim.x) {
        float4 v = ((const float4*)src)[i];
        ((uint2*)dst)[i] = make_uint2(packh2(v.x, v.y), packh2(v.z, v.w));
    }
}

// ===========================================================================
// Plain fp16 GEMM mainloop: D = A * B^T, K-step 32, 3 stages, wait1,
// XOR-swizzled 64B-pitch tiles. Stage = 2 tiles (A, B). 32 MMAs/iter.
// ===========================================================================
#define GP_B        64
#define TILE_B      (128*GP_B)          // 8192
#define STAGE_B     (2*TILE_B)          // 16384
#define GSMEM       (3*STAGE_B)         // 49152

__device__ __forceinline__ uint32_t gsw(int row, int chunk) {
    return (uint32_t)(row * GP_B + ((chunk ^ ((row >> 1) & 3)) << 4));
}

__device__ __forceinline__ void gemm_mainloop(
    const __half* __restrict__ A, const __half* __restrict__ B,
    int m0, int n0, char* sm, float acc[4][4][4])
{
    const int tid = threadIdx.x;
    const uint32_t smb = smem_u32(sm);

    #pragma unroll
    for (int t = 0; t < 4; t++)
        #pragma unroll
        for (int n = 0; n < 4; n++)
            #pragma unroll
            for (int e = 0; e < 4; e++) acc[t][n][e] = 0.0f;

    auto load_stage = [&](int st, int k0) {
        uint32_t base = smb + st * STAGE_B;
        #pragma unroll
        for (int j = 0; j < 2; j++) {
            int idx = tid + j * 256;
            int r = idx >> 2, c = idx & 3;
            uint32_t doff = gsw(r, c);
            cp16(base + doff,          A + (size_t)(m0 + r) * DD + k0 + c * 8);
            cp16(base + TILE_B + doff, B + (size_t)(n0 + r) * DD + k0 + c * 8);
        }
    };

    load_stage(0, 0);  CP_COMMIT;
    load_stage(1, 32); CP_COMMIT;

    const int wid = tid >> 5, lane = tid & 31;
    const int wm = (wid >> 2) * 64;
    const int wn = (wid & 3) * 32;
    const int arow = lane & 15;
    const int ack  = lane >> 4;
    const int brow = (lane & 7) + ((lane >> 4) << 3);
    const int bck  = (lane >> 3) & 1;

    int stage = 0;
    for (int kt = 0; kt < 32; kt++) {
        CP_WAIT1;
        __syncthreads();
        if (kt + 2 < 32) {
            int st2 = stage + 2; if (st2 >= 3) st2 -= 3;
            load_stage(st2, (kt + 2) * 32);
            CP_COMMIT;
        }

        uint32_t base = smb + stage * STAGE_B;
        uint32_t sA = base, sB = base + TILE_B;

        #pragma unroll
        for (int k16 = 0; k16 < 2; k16++) {
            uint32_t ah[4][4], bh[4][2];
            #pragma unroll
            for (int t = 0; t < 4; t++)
                ldsm4(ah[t], sA + gsw(wm + t*16 + arow, k16*2 + ack));
            #pragma unroll
            for (int p = 0; p < 2; p++) {
                uint32_t bo = gsw(wn + p*16 + brow, k16*2 + bck);
                uint32_t r4[4];
                ldsm4(r4, sB + bo);
                bh[2*p][0] = r4[0]; bh[2*p][1] = r4[1];
                bh[2*p+1][0] = r4[2]; bh[2*p+1][1] = r4[3];
            }
            #pragma unroll
            for (int t = 0; t < 4; t++)
                #pragma unroll
                for (int n = 0; n < 4; n++)
                    mma16816h(acc[t][n], ah[t], bh[n]);
        }

        if (++stage == 3) stage = 0;
    }
}

// ---------------------------------------------------------------------------
// Q/K/V projection: ONE kernel, uniform fp16-single epilogue.
// grid.x=24 (q:0-7, k:8-15, v:16-23)
// ---------------------------------------------------------------------------
__global__ __launch_bounds__(256, 2) void qkv_gemm_mma()
{
    extern __shared__ char sm[];
    const int which = blockIdx.x >> 3;      // 0=q, 1=k, 2=v
    const int nb = (blockIdx.x & 7) * 128;
    const int m0 = blockIdx.y * 128;

    __half* OUT = (which == 0) ? g_qh : (which == 1) ? g_kh : g_vh;

    float acc[4][4][4];
    gemm_mainloop(g_xh, g_wh[which], m0, nb, sm, acc);

    const int tid = threadIdx.x, wid = tid >> 5, lane = tid & 31;
    const int wm = (wid >> 2) * 64, wn = (wid & 3) * 32;
    const int gid = lane >> 2, qid = lane & 3;

    #pragma unroll
    for (int t = 0; t < 4; t++) {
        #pragma unroll
        for (int n = 0; n < 4; n++) {
            int cc = nb + wn + n*8 + qid*2;
            int h = cc >> 6, hd = cc & 63;
            #pragma unroll
            for (int half = 0; half < 2; half++) {
                int row = m0 + wm + t*16 + gid + 8*half;
                int b = row >> 11, s = row & 2047;
                size_t off = (((size_t)(b*NH + h))*SB + s)*HDIM + hd;
                *(uint32_t*)&OUT[off] = packh2(acc[t][n][2*half],
                                               acc[t][n][2*half+1]);
            }
        }
    }
}

// ---------------------------------------------------------------------------
// Output projection: out = ctx @ Wo^T + bo (fp32 out)
// ---------------------------------------------------------------------------
__global__ __launch_bounds__(256, 2) void out_gemm_mma(
    const float* __restrict__ bo, float* __restrict__ OUT)
{
    extern __shared__ char sm[];
    const int n0 = blockIdx.x * 128;
    const int m0 = blockIdx.y * 128;

    float acc[4][4][4];
    gemm_mainloop(g_ch, g_wh[3], m0, n0, sm, acc);

    const int tid = threadIdx.x, wid = tid >> 5, lane = tid & 31;
    const int wm = (wid >> 2) * 64, wn = (wid & 3) * 32;
    const int gid = lane >> 2, qid = lane & 3;

    #pragma unroll
    for (int t = 0; t < 4; t++) {
        #pragma unroll
        for (int n = 0; n < 4; n++) {
            int cn = n0 + wn + n*8 + qid*2;
            float2 bb = *(const float2*)&bo[cn];
            #pragma unroll
            for (int half = 0; half < 2; half++) {
                int row = m0 + wm + t*16 + gid + 8*half;
                float2 v = make_float2(acc[t][n][2*half] + bb.x,
                                       acc[t][n][2*half + 1] + bb.y);
                *(float2*)&OUT[(size_t)row * DD + cn] = v;
            }
        }
    }
}

// ===========================================================================
// Flash attention, all single fp16:
//   QK: 32 MMAs/step (Q single fp16 from gmem, K single fp16)
//   PV: 32 MMAs/step (P fp16, V fp16)
// 3 KV stages of (K fp16 + V fp16) = 18432 B each, wait1, prefetch 2 ahead.
// Per-warp skip of fully-masked blocks; mask math only on diagonal blocks.
// ===========================================================================
#define FP_B  144                    // smem pitch bytes (72 halves)
#define BUF_B  (64*FP_B)             // 9216
#define STG_B  (2*BUF_B)             // 18432
#define FA_SMEM (3*STG_B)            // 55296
#define SCL2  0.18033688f            // 0.125 * log2(e)

__global__ __launch_bounds__(256, 2) void flash_attn_mma()
{
    extern __shared__ char smc[];
    const uint32_t smb = smem_u32(smc);

    const int qt = (int)gridDim.x - 1 - (int)blockIdx.x;   // heavy first
    const int bh = blockIdx.y;
    const int q0 = qt * 128;

    const int tid = threadIdx.x, w = tid >> 5, lane = tid & 31;
    const int wm = w * 16;

    const __half* Qp = g_qh + ((size_t)bh*SB + q0)*HDIM;
    const __half* Kp = g_kh + (size_t)bh*SB*HDIM;
    const __half* Vp = g_vh + (size_t)bh*SB*HDIM;

    auto load_kv = [&](int st, int c0) {
        uint32_t base = smb + st*STG_B;
        for (int idx = tid; idx < 1024; idx += 256) {
            int buf = idx >> 9, r = (idx >> 3) & 63, c = idx & 7;
            const __half* sp = (buf ? Vp : Kp) + (size_t)(c0 + r)*64 + c*8;
            cp16(base + buf*BUF_B + r*FP_B + c*16, sp);
        }
    };

    const int nsteps = 2*(qt + 1);
    load_kv(0, 0);  CP_COMMIT;
    load_kv(1, 64); CP_COMMIT;

    // ---- Q fragments: direct gmem loads (A-frag lane map, 4B each) ----
    const int g  = lane >> 2;
    const int q2 = (lane & 3) * 2;
    uint32_t qa[4][4];
    #pragma unroll
    for (int kc = 0; kc < 4; kc++)
        #pragma unroll
        for (int rr = 0; rr < 4; rr++) {
            int row = wm + g + ((rr & 1) << 3);
            int col = kc*16 + q2 + ((rr >> 1) << 3);
            qa[kc][rr] = *(const uint32_t*)(Qp + (size_t)row*HDIM + col);
        }

    float m0v = -INFINITY, m1v = -INFINITY, l0v = 0.0f, l1v = 0.0f;
    float oc[8][4];
    #pragma unroll
    for (int j = 0; j < 8; j++)
        #pragma unroll
        for (int e = 0; e < 4; e++) oc[j][e] = 0.0f;

    const int brow = (lane & 7) + ((lane >> 4) << 3);
    const int bkk  = ((lane >> 3) & 1) << 3;
    const int vrow = (lane & 7) + (((lane >> 3) & 1) << 3);
    const int vc8  = (lane >> 4) << 3;
    const int r0   = q0 + wm + (lane >> 2);
    const int rmax = q0 + wm + 15;         // last row this warp owns

    int stage = 0;
    for (int kt = 0; kt < nsteps; kt++) {
        const int c0 = kt * 64;
        CP_WAIT1;
        __syncthreads();
        if (kt + 2 < nsteps) {
            int st2 = stage + 2; if (st2 >= 3) st2 -= 3;
            load_kv(st2, (kt + 2)*64);
            CP_COMMIT;
        }

        // Fully-masked block for this warp -> nothing to do (barriers only).
        if (c0 > rmax) { if (++stage == 3) stage = 0; continue; }

        const uint32_t sK = smb + stage*STG_B;
        const uint32_t sV = sK + BUF_B;

        // ---- S = Q K^T (single fp16) ----
        float sc[8][4];
        #pragma unroll
        for (int j = 0; j < 8; j++)
            #pragma unroll
            for (int e = 0; e < 4; e++) sc[j][e] = 0.0f;

        #pragma unroll
        for (int k16 = 0; k16 < 4; k16++) {
            uint32_t kk[8][2];
            #pragma unroll
            for (int j2 = 0; j2 < 4; j2++) {
                uint32_t off = (uint32_t)((j2*16 + brow)*FP_B + (k16*16 + bkk)*2);
                uint32_t r4[4];
                ldsm4(r4, sK + off);
                kk[2*j2][0] = r4[0]; kk[2*j2][1] = r4[1];
                kk[2*j2+1][0] = r4[2]; kk[2*j2+1][1] = r4[3];
            }
            #pragma unroll
            for (int j = 0; j < 8; j++) mma16816h(sc[j], qa[k16], kk[j]);
        }

        // ---- scale (log2 domain); mask only on boundary blocks ----
        if (c0 + 64 > q0 + wm) {          // block crosses/touches the diagonal
            #pragma unroll
            for (int j = 0; j < 8; j++) {
                int cb = c0 + j*8 + (lane & 3)*2;
                #pragma unroll
                for (int e = 0; e < 4; e++) {
                    float v = sc[j][e] * SCL2;
                    int col = cb + (e & 1);
                    int row = r0 + ((e >> 1) << 3);
                    if (col > row) v = -INFINITY;
                    sc[j][e] = v;
                }
            }
        } else {
            #pragma unroll
            for (int j = 0; j < 8; j++)
                #pragma unroll
                for (int e = 0; e < 4; e++)
                    sc[j][e] *= SCL2;
        }

        // ---- online softmax (base-2) ----
        float mx0 = sc[0][0], mx1 = sc[0][2];
        #pragma unroll
        for (int j = 0; j < 8; j++) {
            mx0 = fmaxf(mx0, fmaxf(sc[j][0], sc[j][1]));
            mx1 = fmaxf(mx1, fmaxf(sc[j][2], sc[j][3]));
        }
        mx0 = fmaxf(mx0, __shfl_xor_sync(0xffffffffu, mx0, 1));
        mx0 = fmaxf(mx0, __shfl_xor_sync(0xffffffffu, mx0, 2));
        mx1 = fmaxf(mx1, __shfl_xor_sync(0xffffffffu, mx1, 1));
        mx1 = fmaxf(mx1, __shfl_xor_sync(0xffffffffu, mx1, 2));

        float mn0 = fmaxf(m0v, mx0), mn1 = fmaxf(m1v, mx1);
        float al0 = exp2f(m0v - mn0), al1 = exp2f(m1v - mn1);
        m0v = mn0; m1v = mn1;

        float s0 = 0.0f, s1 = 0.0f;
        #pragma unroll
        for (int j = 0; j < 8; j++) {
            sc[j][0] = exp2f(sc[j][0] - mn0); s0 += sc[j][0];
            sc[j][1] = exp2f(sc[j][1] - mn0); s0 += sc[j][1];
            sc[j][2] = exp2f(sc[j][2] - mn1); s1 += sc[j][2];
            sc[j][3] = exp2f(sc[j][3] - mn1); s1 += sc[j][3];
        }
        s0 += __shfl_xor_sync(0xffffffffu, s0, 1);
        s0 += __shfl_xor_sync(0xffffffffu, s0, 2);
        s1 += __shfl_xor_sync(0xffffffffu, s1, 1);
        s1 += __shfl_xor_sync(0xffffffffu, s1, 2);
        l0v = l0v * al0 + s0;
        l1v = l1v * al1 + s1;
        #pragma unroll
        for (int j = 0; j < 8; j++) {
            oc[j][0] *= al0; oc[j][1] *= al0;
            oc[j][2] *= al1; oc[j][3] *= al1;
        }

        // ---- pack P to fp16 single (C-frag == A-frag layout) ----
        uint32_t pa[4][4];
        #pragma unroll
        for (int t = 0; t < 4; t++) {
            pa[t][0] = packh2(sc[2*t][0],   sc[2*t][1]);
            pa[t][1] = packh2(sc[2*t][2],   sc[2*t][3]);
            pa[t][2] = packh2(sc[2*t+1][0], sc[2*t+1][1]);
            pa[t][3] = packh2(sc[2*t+1][2], sc[2*t+1][3]);
        }

        // ---- O += P V (single fp16) ----
        #pragma unroll
        for (int k16 = 0; k16 < 4; k16++) {
            uint32_t vv[8][2];
            #pragma unroll
            for (int n16 = 0; n16 < 4; n16++) {
                uint32_t off = (uint32_t)((k16*16 + vrow)*FP_B + (n16*16 + vc8)*2);
                uint32_t r4[4];
                ldsm4t(r4, sV + off);
                vv[2*n16][0] = r4[0]; vv[2*n16][1] = r4[1];
                vv[2*n16+1][0] = r4[2]; vv[2*n16+1][1] = r4[3];
            }
            #pragma unroll
            for (int j = 0; j < 8; j++) mma16816h(oc[j], pa[k16], vv[j]);
        }

        if (++stage == 3) stage = 0;
    }

    // ---- finalize, write ctx as fp16 (out_gemm A operand) ----
    const float inv0 = 1.0f / l0v, inv1 = 1.0f / l1v;
    const int b = bh / NH, h = bh % NH;
    const int row0 = q0 + wm + (lane >> 2);
    #pragma unroll
    for (int j = 0; j < 8; j++) {
        int col = h*64 + j*8 + (lane & 3)*2;
        size_t off0 = ((size_t)(b*SB + row0))*DD + col;
        *(uint32_t*)&g_ch[off0] = packh2(oc[j][0]*inv0, oc[j][1]*inv0);
        size_t off1 = ((size_t)(b*SB + row0 + 8))*DD + col;
        *(uint32_t*)&g_ch[off1] = packh2(oc[j][2]*inv1, oc[j][3]*inv1);
    }
}

// ---------------------------------------------------------------------------
extern "C" void kernel_launch(void* const* d_in, const int* in_sizes, int n_in,
                              void* d_out, int out_size)
{
    const float* x  = (const float*)d_in[0];
    const float* Wq = (const float*)d_in[1];
    const float* Wk = (const float*)d_in[2];
    const float* Wv = (const float*)d_in[3];
    const float* Wo = (const float*)d_in[4];
    const float* bo = (const float*)d_in[5];
    float* out = (float*)d_out;

    cudaFuncSetAttribute(qkv_gemm_mma,   cudaFuncAttributeMaxDynamicSharedMemorySize, GSMEM);
    cudaFuncSetAttribute(out_gemm_mma,   cudaFuncAttributeMaxDynamicSharedMemorySize, GSMEM);
    cudaFuncSetAttribute(flash_attn_mma, cudaFuncAttributeMaxDynamicSharedMemorySize, FA_SMEM);

    convert_all<<<dim3(160, 5), 256>>>(x, Wq, Wk, Wv, Wo);
    qkv_gemm_mma<<<dim3(24, 32), 256, GSMEM>>>();
    flash_attn_mma<<<dim3(SB/128, BB*NH), 256, FA_SMEM>>>();
    out_gemm_mma<<<dim3(8, 32), 256, GSMEM>>>(bo, out);
}